// round 5
// baseline (speedup 1.0000x reference)
#include <cuda_runtime.h>
#include <cuda_bf16.h>

// Problem constants
#define Bn 4
#define Hn 480
#define Wn 640
#define HWn (Hn * Wn)          // 307200
#define PWn (Wn + 2)           // 642
#define PHn (Hn + 2)           // 482
#define PHWn (PHn * PWn)       // 309444
#define PROP_TIME 18

// OOB sentinel: row 481 (zero border); +PWn lands in next batch's zero row 0
// or the zero tail for the last batch.
#define OOB_OFF ((PHn - 1) * PWn)   // 308802 (even)
#define TAIL 704

// Static scratch. Each logical feature buffer has two copies:
//  *0[i] = g[i]  and  *S[i] = g[i+1]  (shifted) so any adjacent pair
// (off, off+1) is readable as ONE aligned float2 from one of the copies.
__device__ float g_bufA0[Bn * PHWn + TAIL];
__device__ float g_bufAs[Bn * PHWn + TAIL];
__device__ float g_bufB0[Bn * PHWn + TAIL];
__device__ float g_bufBs[Bn * PHWn + TAIL];
// Packed per-tap data, layout [b][tap][pix], 8 bytes per entry:
//   lo: off(19 bits) | wxq(13 bits)<<19
//   hi: wyq(13 bits) | affq(signed 19-bit)<<13
__device__ ulonglong2 g_taps[Bn * 8 * HWn / 2];
// Fused fix/conf: q<0 -> fixed pixel value -q; q>=0 -> conf=q.
__device__ float g_q[Bn * HWn];

// ---------------------------------------------------------------------------
// Precompute (idempotent; replayed each graph launch).
// ---------------------------------------------------------------------------
__global__ __launch_bounds__(256)
void prep_kernel(const float* __restrict__ feat_init,
                 const float* __restrict__ guid,
                 const float* __restrict__ conf,
                 const float* __restrict__ fix,
                 const float* __restrict__ scale_ptr)
{
    int idx = blockIdx.x * blockDim.x + threadIdx.x;
    if (idx >= Bn * PHWn + TAIL) return;

    int b = idx / PHWn;
    int r = idx - b * PHWn;
    int yy = r / PWn;
    int xx = r - yy * PWn;

    bool is_tail = (idx >= Bn * PHWn);
    bool is_border = is_tail || (yy == 0) || (yy == PHn - 1) || (xx == 0) || (xx == PWn - 1);

    if (is_border) {
        // val(idx) = 0: direct copies get 0 at idx; shifted copies get 0 at idx-1.
        g_bufA0[idx] = 0.0f;
        g_bufB0[idx] = 0.0f;
        if (idx >= 1) {
            g_bufAs[idx - 1] = 0.0f;
            g_bufBs[idx - 1] = 0.0f;
        }
        if (is_tail) {             // also zero shifted tails at idx itself
            g_bufAs[idx] = 0.0f;
            g_bufBs[idx] = 0.0f;
        }
        return;
    }

    int y = yy - 1, x = xx - 1;
    int pix = y * Wn + x;

    // Affinity normalization (guidance channels 16..23)
    float scale = scale_ptr[0] + 1e-8f;
    float inv_scale = 1.0f / scale;
    const float* gbase = guid + ((size_t)b * 24) * HWn + pix;
    float a[8];
    float s = 1e-4f;
#pragma unroll
    for (int k = 0; k < 8; k++) {
        float v = tanhf(gbase[(16 + k) * HWn]) * inv_scale;
        a[k] = v;
        s += fabsf(v);
    }
    s = fmaxf(s, 1.0f);
    float invs = 1.0f / s;

#pragma unroll
    for (int t = 0; t < 8; t++) {
        const int kt = (t < 4) ? t : t + 1;
        const float ky = (float)(kt / 3 - 1);
        const float kx = (float)(kt % 3 - 1);

        float dy = gbase[(2 * t) * HWn];
        float dx = gbase[(2 * t + 1) * HWn];

        float py = (float)y + ky + dy;
        float px = (float)x + kx + dx;
        float y0f = floorf(py);
        float x0f = floorf(px);
        int iy = (int)y0f;
        int ix = (int)x0f;
        float wy = py - y0f;
        float wx = px - x0f;

        bool valid = (iy >= -1) & (iy <= Hn - 1) & (ix >= -1) & (ix <= Wn - 1);
        unsigned int off = valid ? (unsigned int)((iy + 1) * PWn + (ix + 1))
                                 : (unsigned int)OOB_OFF;
        int wxq = min((int)(wx * 8192.0f + 0.5f), 8191);
        int wyq = min((int)(wy * 8192.0f + 0.5f), 8191);
        int affq = (int)rintf(a[t] * invs * 131072.0f);

        unsigned int lo = off | ((unsigned int)wxq << 19);
        unsigned int hi = (unsigned int)wyq | ((unsigned int)affq << 13);
        unsigned long long word = ((unsigned long long)hi << 32) | lo;
        unsigned long long* tp =
            reinterpret_cast<unsigned long long*>(g_taps) +
            ((size_t)(b * 8 + t) * HWn + pix);
        *tp = word;
    }

    int gidx = b * HWn + pix;
    float fv = fix[gidx];
    bool m = fv > 0.0f;
    float cf = conf[gidx];
    float f0 = m ? fv : feat_init[gidx];
    float ce = m ? 1.0f : cf;
    float g0v = f0 * ce;
    g_bufA0[idx] = g0v;
    g_bufAs[idx - 1] = g0v;        // idx >= 1 for interior
    g_q[gidx] = m ? -fv : cf;
}

// ---------------------------------------------------------------------------
// One propagation step: 2 px/thread, float2 gathers via dual shifted copies.
// ---------------------------------------------------------------------------
__device__ __forceinline__ float bilerp_tap(unsigned long long w,
                                            const float* __restrict__ in0,
                                            const float* __restrict__ inS,
                                            float& asum, float& acc)
{
    unsigned int lo = (unsigned int)w;
    unsigned int hi = (unsigned int)(w >> 32);
    unsigned int off = lo & 0x7FFFFu;
    float wx = (float)(lo >> 19) * (1.0f / 8192.0f);
    float wy = (float)(hi & 0x1FFFu) * (1.0f / 8192.0f);
    float av = (float)(((int)hi) >> 13) * (1.0f / 131072.0f);

    const float* base = (off & 1u) ? inS : in0;
    unsigned int e = off & ~1u;
    float2 t0 = *reinterpret_cast<const float2*>(base + e);        // v00,v01
    float2 b0 = *reinterpret_cast<const float2*>(base + e + PWn);  // v10,v11
    float top = fmaf(wx, t0.y - t0.x, t0.x);
    float bot = fmaf(wx, b0.y - b0.x, b0.x);
    float v = fmaf(wy, bot - top, top);
    acc = fmaf(av, v, acc);
    asum += av;
    return v;
}

__global__ __launch_bounds__(256)
void iter_kernel(float* __restrict__ outF, int srcIsA, int write_out)
{
    int i = blockIdx.x * blockDim.x + threadIdx.x;
    if (i >= Bn * HWn / 2) return;
    int p = i * 2;
    int b = p / HWn;
    int r = p - b * HWn;
    int y = r / Wn;
    int x = r - y * Wn;

    const float* __restrict__ in0 = (srcIsA ? g_bufA0 : g_bufB0) + (size_t)b * PHWn;
    const float* __restrict__ inS = (srcIsA ? g_bufAs : g_bufBs) + (size_t)b * PHWn;
    const ulonglong2* __restrict__ taps = g_taps + (size_t)b * 8 * (HWn / 2) + (r >> 1);

    float acc0 = 0.0f, acc1 = 0.0f;
    float asum0 = 0.0f, asum1 = 0.0f;

#pragma unroll
    for (int t = 0; t < 8; t++) {
        ulonglong2 tv = taps[t * (HWn / 2)];
        bilerp_tap(tv.x, in0, inS, asum0, acc0);
        bilerp_tap(tv.y, in0, inS, asum1, acc1);
    }

    // Center taps: exact samples; affinity = 1 - sum(aff8).
    int cbase = (y + 1) * PWn + (x + 1);
    float c0 = in0[cbase];
    float c1 = in0[cbase + 1];
    acc0 = fmaf(1.0f - asum0, c0, acc0);
    acc1 = fmaf(1.0f - asum1, c1, acc1);

    float2 qv = *reinterpret_cast<const float2*>(g_q + p);
    bool m0 = qv.x < 0.0f;
    bool m1 = qv.y < 0.0f;
    float fn0 = m0 ? -qv.x : acc0;
    float fn1 = m1 ? -qv.y : acc1;

    if (write_out) {
        *reinterpret_cast<float2*>(outF + p) = make_float2(fn0, fn1);
    } else {
        float g0 = m0 ? fn0 : fn0 * qv.x;
        float g1 = m1 ? fn1 : fn1 * qv.y;
        float* o0 = (srcIsA ? g_bufB0 : g_bufA0) + (size_t)b * PHWn;
        float* oS = (srcIsA ? g_bufBs : g_bufAs) + (size_t)b * PHWn;
        o0[cbase]     = g0;
        o0[cbase + 1] = g1;
        oS[cbase - 1] = g0;   // oS[j] = g[j+1]
        oS[cbase]     = g1;
    }
}

extern "C" void kernel_launch(void* const* d_in, const int* in_sizes, int n_in,
                              void* d_out, int out_size)
{
    const float* feat_init  = (const float*)d_in[0];
    const float* guidance   = (const float*)d_in[1];
    const float* confidence = (const float*)d_in[2];
    const float* feat_fix   = (const float*)d_in[3];
    const float* aff_scale  = (const float*)d_in[4];
    float* out = (float*)d_out;

    const int threads = 256;
    const int prep_blocks = (Bn * PHWn + TAIL + threads - 1) / threads;
    const int iter_blocks = (Bn * HWn / 2 + threads - 1) / threads;

    prep_kernel<<<prep_blocks, threads>>>(feat_init, guidance, confidence,
                                          feat_fix, aff_scale);

    int srcIsA = 1;
    for (int t = 0; t < PROP_TIME; t++) {
        int last = (t == PROP_TIME - 1) ? 1 : 0;
        iter_kernel<<<iter_blocks, threads>>>(out, srcIsA, last);
        srcIsA ^= 1;
    }
}